// round 16
// baseline (speedup 1.0000x reference)
#include <cuda_runtime.h>

typedef unsigned long long u64;

#define TPB 128
// element strides in u64 units; 21 mod 16 = 5, 17 mod 16 = 1 (coprime 16)
// -> conflict-free scalar LDS.64 across 16-lane phases (R10-proven)
#define STRIDE10 21
#define STRIDE8  17

// ---- packed f32x2 helpers ----
__device__ __forceinline__ u64 pk2(float lo, float hi) {
    u64 r; asm("mov.b64 %0,{%1,%2};" : "=l"(r) : "f"(lo), "f"(hi)); return r;
}
__device__ __forceinline__ float2 unpk(u64 v) {
    float2 f; asm("mov.b64 {%0,%1},%2;" : "=f"(f.x), "=f"(f.y) : "l"(v)); return f;
}
__device__ __forceinline__ u64 fma2(u64 a, u64 b, u64 c) {
    u64 d; asm("fma.rn.f32x2 %0,%1,%2,%3;" : "=l"(d) : "l"(a), "l"(b), "l"(c)); return d;
}
__device__ __forceinline__ u64 relu2(u64 v) {
    float2 f = unpk(v);
    return pk2(fmaxf(f.x, 0.f), fmaxf(f.y, 0.f));
}

// ---- constant-bank layout (u64 units): ALL weights + biases, {w,w}-duplicated ----
#define C_EW1 0
#define C_EB1 100
#define C_EW2 110
#define C_EB2 210
#define C_EW3 220
#define C_EB3 230
#define C_XW1 231
#define C_XB1 295
#define C_XW2 303
#define C_XB2 367
#define C_XW3 375
#define C_XB3 383
#define C_CW1 384
#define C_CB1 484
#define C_CW2 494
#define C_CB2 594
#define C_CW3 604
#define C_CB3 614
#define C_NW  615
#define C_NB  616
#define NCONST 617

__constant__ u64 cwt[NCONST];
__device__ u64 g_stage[NCONST];   // staging for D2D copy into cwt

// ---- shared layout (u64 units): staged inputs ONLY ----
#define O_EDGE   0
#define O_CROSS  (O_EDGE + TPB * STRIDE10)            // 2688
#define O_CORNER (O_CROSS + TPB * STRIDE8)            // 4864
#define SMEM_U64 (O_CORNER + TPB * STRIDE10)          // 7552
#define SMEM_BYTES (SMEM_U64 * 8)                     // 60416 -> 3 CTAs/SM

// 3-layer MLP over 4 slices as two f32x2 pairs sharing each weight fetch.
// ALL weights come from the CONSTANT port (uniform path, immediate offsets);
// the shared crossbar carries only input loads. The two paths run in parallel.
template <int D, int W1, int B1, int W2, int B2, int W3, int B3>
__device__ __forceinline__ float mlp_sum4(const u64* __restrict__ xe) {
    u64 x0[D], x1[D], h0[D], h1[D];
#pragma unroll
    for (int i = 0; i < D; i++) { x0[i] = xe[i * 2]; x1[i] = xe[i * 2 + 1]; }
    // layer 1 + relu
#pragma unroll
    for (int o = 0; o < D; o++) {
        u64 b = cwt[B1 + o], a0 = b, a1 = b;
#pragma unroll
        for (int i = 0; i < D; i++) {
            u64 w = cwt[W1 + o * D + i];
            a0 = fma2(x0[i], w, a0);
            a1 = fma2(x1[i], w, a1);
        }
        h0[o] = relu2(a0); h1[o] = relu2(a1);
    }
    // layer 2 + relu (write back into x arrays)
#pragma unroll
    for (int o = 0; o < D; o++) {
        u64 b = cwt[B2 + o], a0 = b, a1 = b;
#pragma unroll
        for (int i = 0; i < D; i++) {
            u64 w = cwt[W2 + o * D + i];
            a0 = fma2(h0[i], w, a0);
            a1 = fma2(h1[i], w, a1);
        }
        x0[o] = relu2(a0); x1[o] = relu2(a1);
    }
    // layer 3 (linear, out dim 1)
    u64 b = cwt[B3], a0 = b, a1 = b;
#pragma unroll
    for (int i = 0; i < D; i++) {
        u64 w = cwt[W3 + i];
        a0 = fma2(x0[i], w, a0);
        a1 = fma2(x1[i], w, a1);
    }
    float2 f0 = unpk(a0), f1 = unpk(a1);
    return f0.x + f0.y + f1.x + f1.y;
}

// Coalesced stage of TPB elements x (4*D) floats into shared, pair-interleaved:
// element e, feature i, slice s -> e*STRIDE*2 + i*4 + s (floats).
template <int D, int STRIDE>
__device__ __forceinline__ void stage(const float* __restrict__ g, float* __restrict__ s, int tid) {
    const float4* g4 = (const float4*)g;
#pragma unroll
    for (int k = 0; k < D; k++) {
        int f = k * TPB + tid;
        float4 v = g4[f];
        int elem = f / D;
        int j = f - elem * D;
        float vv[4] = {v.x, v.y, v.z, v.w};
        float* base = s + elem * (STRIDE * 2);
#pragma unroll
        for (int c = 0; c < 4; c++) {
            int within = j * 4 + c;     // 0..4D-1, slice-major in gmem
            int sl = within / D;
            int i  = within - sl * D;
            base[i * 4 + sl] = vv[c];
        }
    }
}

// Prep kernel: duplicate ALL weights into g_stage as {w,w} u64.
__global__ void osero_prep(const float* __restrict__ eW1, const float* __restrict__ eb1,
                           const float* __restrict__ eW2, const float* __restrict__ eb2,
                           const float* __restrict__ eW3, const float* __restrict__ eb3,
                           const float* __restrict__ xW1, const float* __restrict__ xb1,
                           const float* __restrict__ xW2, const float* __restrict__ xb2,
                           const float* __restrict__ xW3, const float* __restrict__ xb3,
                           const float* __restrict__ cW1, const float* __restrict__ cb1,
                           const float* __restrict__ cW2, const float* __restrict__ cb2,
                           const float* __restrict__ cW3, const float* __restrict__ cb3,
                           const float* __restrict__ nW,  const float* __restrict__ nb) {
    int tid = threadIdx.x;
    auto dup = [&](int off, const float* src, int n) {
        for (int i = tid; i < n; i += blockDim.x) { float v = src[i]; g_stage[off + i] = pk2(v, v); }
    };
    dup(C_EW1, eW1, 100); dup(C_EB1, eb1, 10);
    dup(C_EW2, eW2, 100); dup(C_EB2, eb2, 10);
    dup(C_EW3, eW3, 10);  dup(C_EB3, eb3, 1);
    dup(C_XW1, xW1, 64);  dup(C_XB1, xb1, 8);
    dup(C_XW2, xW2, 64);  dup(C_XB2, xb2, 8);
    dup(C_XW3, xW3, 8);   dup(C_XB3, xb3, 1);
    dup(C_CW1, cW1, 100); dup(C_CB1, cb1, 10);
    dup(C_CW2, cW2, 100); dup(C_CB2, cb2, 10);
    dup(C_CW3, cW3, 10);  dup(C_CB3, cb3, 1);
    dup(C_NW,  nW,  1);   dup(C_NB,  nb,  1);
}

__global__ __launch_bounds__(TPB, 3)
void osero_kernel(const float* __restrict__ edge, const float* __restrict__ cross,
                  const float* __restrict__ corner, const float* __restrict__ cn,
                  float* __restrict__ out) {
    extern __shared__ u64 dsm[];

    const int tid = threadIdx.x;
    const long long e0 = (long long)blockIdx.x * TPB;

    // ---- stage ALL inputs first: 30 LDG.128 in flight per thread ----
    stage<10, STRIDE10>(edge   + e0 * 40, (float*)(dsm + O_EDGE),   tid);
    stage<8,  STRIDE8 >(cross  + e0 * 32, (float*)(dsm + O_CROSS),  tid);
    stage<10, STRIDE10>(corner + e0 * 40, (float*)(dsm + O_CORNER), tid);
    const float cnv = cn[e0 + tid];

    __syncthreads();   // the ONLY barrier

    float acc = mlp_sum4<10, C_EW1, C_EB1, C_EW2, C_EB2, C_EW3, C_EB3>(
                    dsm + O_EDGE + tid * STRIDE10);
    acc += mlp_sum4<8, C_XW1, C_XB1, C_XW2, C_XB2, C_XW3, C_XB3>(
                    dsm + O_CROSS + tid * STRIDE8);
    acc += mlp_sum4<10, C_CW1, C_CB1, C_CW2, C_CB2, C_CW3, C_CB3>(
                    dsm + O_CORNER + tid * STRIDE10);

    float2 nwv = unpk(cwt[C_NW]);
    float2 nbv = unpk(cwt[C_NB]);
    acc += cnv * nwv.x + nbv.x;
    out[e0 + tid] = acc;
}

extern "C" void kernel_launch(void* const* d_in, const int* in_sizes, int n_in,
                              void* d_out, int out_size) {
    const float* edge   = (const float*)d_in[0];
    const float* cross  = (const float*)d_in[1];
    const float* corner = (const float*)d_in[2];
    const float* cn     = (const float*)d_in[3];
    const float* eW1 = (const float*)d_in[4];
    const float* eb1 = (const float*)d_in[5];
    const float* eW2 = (const float*)d_in[6];
    const float* eb2 = (const float*)d_in[7];
    const float* eW3 = (const float*)d_in[8];
    const float* eb3 = (const float*)d_in[9];
    const float* xW1 = (const float*)d_in[10];
    const float* xb1 = (const float*)d_in[11];
    const float* xW2 = (const float*)d_in[12];
    const float* xb2 = (const float*)d_in[13];
    const float* xW3 = (const float*)d_in[14];
    const float* xb3 = (const float*)d_in[15];
    const float* cW1 = (const float*)d_in[16];
    const float* cb1 = (const float*)d_in[17];
    const float* cW2 = (const float*)d_in[18];
    const float* cb2 = (const float*)d_in[19];
    const float* cW3 = (const float*)d_in[20];
    const float* cb3 = (const float*)d_in[21];
    const float* nW  = (const float*)d_in[22];
    const float* nb  = (const float*)d_in[23];

    int B = in_sizes[0] / 40;          // edge is [B,4,10]
    int blocks = B / TPB;              // 8192

    // 1) duplicate ALL weights into staging buffer (device side)
    osero_prep<<<1, 128>>>(eW1, eb1, eW2, eb2, eW3, eb3,
                           xW1, xb1, xW2, xb2, xW3, xb3,
                           cW1, cb1, cW2, cb2, cW3, cb3, nW, nb);

    // 2) fill the constant bank (resolve real device addresses for both symbols)
    void* cwt_dev = nullptr;
    void* stage_dev = nullptr;
    cudaGetSymbolAddress(&cwt_dev, cwt);
    cudaGetSymbolAddress(&stage_dev, g_stage);
    cudaMemcpyAsync(cwt_dev, stage_dev, NCONST * sizeof(u64),
                    cudaMemcpyDeviceToDevice);

    // 3) main kernel
    cudaFuncSetAttribute(osero_kernel,
                         cudaFuncAttributeMaxDynamicSharedMemorySize, SMEM_BYTES);
    osero_kernel<<<blocks, TPB, SMEM_BYTES>>>(edge, cross, corner, cn,
                                              (float*)d_out);
}

// round 17
// speedup vs baseline: 1.0159x; 1.0159x over previous
#include <cuda_runtime.h>

typedef unsigned long long u64;

#define TPB 128
// element strides in u64 units; 21 mod 16 = 5, 17 mod 16 = 1 (coprime 16)
// -> conflict-free scalar LDS.64 across 16-lane phases (R10-proven)
#define STRIDE10 21
#define STRIDE8  17

// ---- packed f32x2 helpers ----
__device__ __forceinline__ u64 pk2(float lo, float hi) {
    u64 r; asm("mov.b64 %0,{%1,%2};" : "=l"(r) : "f"(lo), "f"(hi)); return r;
}
__device__ __forceinline__ float2 unpk(u64 v) {
    float2 f; asm("mov.b64 {%0,%1},%2;" : "=f"(f.x), "=f"(f.y) : "l"(v)); return f;
}
__device__ __forceinline__ u64 fma2(u64 a, u64 b, u64 c) {
    u64 d; asm("fma.rn.f32x2 %0,%1,%2,%3;" : "=l"(d) : "l"(a), "l"(b), "l"(c)); return d;
}
__device__ __forceinline__ u64 relu2(u64 v) {
    float2 f = unpk(v);
    return pk2(fmaxf(f.x, 0.f), fmaxf(f.y, 0.f));
}

// ---- constant-bank layout (u64 units): layer-2/3 weights + biases ----
// (R14-proven balanced split: W1 via smem crossbar, W2/W3 via const port)
#define C_EW2 0
#define C_EB2 100
#define C_XW2 110
#define C_XB2 174
#define C_CW2 182
#define C_CB2 282
#define C_EW3 292
#define C_EB3 302
#define C_XW3 303
#define C_XB3 311
#define C_CW3 312
#define C_CB3 322
#define C_NW  323
#define C_NB  324
#define NCONST 325

__constant__ u64 cwt[NCONST];
__device__ u64 g_stage[NCONST];   // staging for D2D copy into cwt

// ---- shared layout (u64 units): layer-1 weights + 2 input buffers ----
// corner REUSES the edge buffer -> 41.3KB/CTA -> 4 CTAs/SM (occ 25%)
#define S_EW1 0
#define S_EB1 100
#define S_XW1 110
#define S_XB1 174
#define S_CW1 182
#define S_CB1 282
#define NSW   296
#define O_EDGE   NSW
#define O_CROSS  (O_EDGE + TPB * STRIDE10)            // 296 + 2688 = 2984
#define O_CORNER O_EDGE
#define SMEM_U64 (O_CROSS + TPB * STRIDE8)            // 2984 + 2176 = 5160
#define SMEM_BYTES (SMEM_U64 * 8)                     // 41280 -> 4 CTAs/SM

// 3-layer MLP over 4 slices as two f32x2 pairs sharing each weight fetch.
// Layer 1 weights via SHARED (crossbar); layers 2/3 via CONSTANT port.
template <int D, int CW2, int CB2, int CW3, int CB3>
__device__ __forceinline__ float mlp_sum4(const u64* __restrict__ xe,
                                          const u64* __restrict__ w1,
                                          const u64* __restrict__ b1) {
    u64 x0[D], x1[D], h0[D], h1[D];
#pragma unroll
    for (int i = 0; i < D; i++) { x0[i] = xe[i * 2]; x1[i] = xe[i * 2 + 1]; }
    // layer 1 + relu (weights via smem broadcast LDS.64)
#pragma unroll
    for (int o = 0; o < D; o++) {
        u64 b = b1[o], a0 = b, a1 = b;
#pragma unroll
        for (int i = 0; i < D; i++) {
            u64 w = w1[o * D + i];
            a0 = fma2(x0[i], w, a0);
            a1 = fma2(x1[i], w, a1);
        }
        h0[o] = relu2(a0); h1[o] = relu2(a1);
    }
    // layer 2 + relu (weights via constant port, immediate offsets)
#pragma unroll
    for (int o = 0; o < D; o++) {
        u64 b = cwt[CB2 + o], a0 = b, a1 = b;
#pragma unroll
        for (int i = 0; i < D; i++) {
            u64 w = cwt[CW2 + o * D + i];
            a0 = fma2(h0[i], w, a0);
            a1 = fma2(h1[i], w, a1);
        }
        x0[o] = relu2(a0); x1[o] = relu2(a1);
    }
    // layer 3 (linear, out dim 1; constant port)
    u64 b = cwt[CB3], a0 = b, a1 = b;
#pragma unroll
    for (int i = 0; i < D; i++) {
        u64 w = cwt[CW3 + i];
        a0 = fma2(x0[i], w, a0);
        a1 = fma2(x1[i], w, a1);
    }
    float2 f0 = unpk(a0), f1 = unpk(a1);
    return f0.x + f0.y + f1.x + f1.y;
}

// Coalesced stage of TPB elements x (4*D) floats into shared, pair-interleaved:
// element e, feature i, slice s -> e*STRIDE*2 + i*4 + s (floats).
template <int D, int STRIDE>
__device__ __forceinline__ void stage(const float* __restrict__ g, float* __restrict__ s, int tid) {
    const float4* g4 = (const float4*)g;
#pragma unroll
    for (int k = 0; k < D; k++) {
        int f = k * TPB + tid;
        float4 v = g4[f];
        int elem = f / D;
        int j = f - elem * D;
        float vv[4] = {v.x, v.y, v.z, v.w};
        float* base = s + elem * (STRIDE * 2);
#pragma unroll
        for (int c = 0; c < 4; c++) {
            int within = j * 4 + c;     // 0..4D-1, slice-major in gmem
            int sl = within / D;
            int i  = within - sl * D;
            base[i * 4 + sl] = vv[c];
        }
    }
}

// Prep kernel: duplicate layer-2/3 weights into g_stage as {w,w} u64.
__global__ void osero_prep(const float* __restrict__ eW2, const float* __restrict__ eb2,
                           const float* __restrict__ eW3, const float* __restrict__ eb3,
                           const float* __restrict__ xW2, const float* __restrict__ xb2,
                           const float* __restrict__ xW3, const float* __restrict__ xb3,
                           const float* __restrict__ cW2, const float* __restrict__ cb2,
                           const float* __restrict__ cW3, const float* __restrict__ cb3,
                           const float* __restrict__ nW,  const float* __restrict__ nb) {
    int tid = threadIdx.x;
    auto dup = [&](int off, const float* src, int n) {
        for (int i = tid; i < n; i += blockDim.x) { float v = src[i]; g_stage[off + i] = pk2(v, v); }
    };
    dup(C_EW2, eW2, 100); dup(C_EB2, eb2, 10);
    dup(C_XW2, xW2, 64);  dup(C_XB2, xb2, 8);
    dup(C_CW2, cW2, 100); dup(C_CB2, cb2, 10);
    dup(C_EW3, eW3, 10);  dup(C_EB3, eb3, 1);
    dup(C_XW3, xW3, 8);   dup(C_XB3, xb3, 1);
    dup(C_CW3, cW3, 10);  dup(C_CB3, cb3, 1);
    dup(C_NW,  nW,  1);   dup(C_NB,  nb,  1);
}

__global__ __launch_bounds__(TPB, 4)
void osero_kernel(const float* __restrict__ edge, const float* __restrict__ cross,
                  const float* __restrict__ corner, const float* __restrict__ cn,
                  const float* __restrict__ eW1, const float* __restrict__ eb1,
                  const float* __restrict__ xW1, const float* __restrict__ xb1,
                  const float* __restrict__ cW1, const float* __restrict__ cb1,
                  float* __restrict__ out) {
    extern __shared__ u64 dsm[];
    u64* swts = dsm;

    const int tid = threadIdx.x;
    const long long e0 = (long long)blockIdx.x * TPB;

    // ---- stage edge + cross (18 LDG.128 in flight per thread) ----
    stage<10, STRIDE10>(edge  + e0 * 40, (float*)(dsm + O_EDGE),  tid);
    stage<8,  STRIDE8 >(cross + e0 * 32, (float*)(dsm + O_CROSS), tid);
    const float cnv = cn[e0 + tid];

    // ---- stage layer-1 weights (duplicated into both f32x2 lanes) ----
    {
        auto cp = [&](int off, const float* src, int n) {
            for (int i = tid; i < n; i += TPB) { float v = src[i]; swts[off + i] = pk2(v, v); }
        };
        cp(S_EW1, eW1, 100); cp(S_EB1, eb1, 10);
        cp(S_XW1, xW1, 64);  cp(S_XB1, xb1, 8);
        cp(S_CW1, cW1, 100); cp(S_CB1, cb1, 10);
    }

    __syncthreads();

    float acc = mlp_sum4<10, C_EW2, C_EB2, C_EW3, C_EB3>(
                    dsm + O_EDGE + tid * STRIDE10, swts + S_EW1, swts + S_EB1);
    acc += mlp_sum4<8, C_XW2, C_XB2, C_XW3, C_XB3>(
                    dsm + O_CROSS + tid * STRIDE8, swts + S_XW1, swts + S_XB1);

    __syncthreads();   // all reads of edge buffer done
    stage<10, STRIDE10>(corner + e0 * 40, (float*)(dsm + O_CORNER), tid);
    __syncthreads();

    acc += mlp_sum4<10, C_CW2, C_CB2, C_CW3, C_CB3>(
                    dsm + O_CORNER + tid * STRIDE10, swts + S_CW1, swts + S_CB1);

    float2 nwv = unpk(cwt[C_NW]);
    float2 nbv = unpk(cwt[C_NB]);
    acc += cnv * nwv.x + nbv.x;
    out[e0 + tid] = acc;
}

extern "C" void kernel_launch(void* const* d_in, const int* in_sizes, int n_in,
                              void* d_out, int out_size) {
    const float* edge   = (const float*)d_in[0];
    const float* cross  = (const float*)d_in[1];
    const float* corner = (const float*)d_in[2];
    const float* cn     = (const float*)d_in[3];
    const float* eW1 = (const float*)d_in[4];
    const float* eb1 = (const float*)d_in[5];
    const float* eW2 = (const float*)d_in[6];
    const float* eb2 = (const float*)d_in[7];
    const float* eW3 = (const float*)d_in[8];
    const float* eb3 = (const float*)d_in[9];
    const float* xW1 = (const float*)d_in[10];
    const float* xb1 = (const float*)d_in[11];
    const float* xW2 = (const float*)d_in[12];
    const float* xb2 = (const float*)d_in[13];
    const float* xW3 = (const float*)d_in[14];
    const float* xb3 = (const float*)d_in[15];
    const float* cW1 = (const float*)d_in[16];
    const float* cb1 = (const float*)d_in[17];
    const float* cW2 = (const float*)d_in[18];
    const float* cb2 = (const float*)d_in[19];
    const float* cW3 = (const float*)d_in[20];
    const float* cb3 = (const float*)d_in[21];
    const float* nW  = (const float*)d_in[22];
    const float* nb  = (const float*)d_in[23];

    int B = in_sizes[0] / 40;          // edge is [B,4,10]
    int blocks = B / TPB;              // 8192

    // 1) duplicate layer-2/3 weights into staging buffer (device side)
    osero_prep<<<1, 128>>>(eW2, eb2, eW3, eb3, xW2, xb2, xW3, xb3,
                           cW2, cb2, cW3, cb3, nW, nb);

    // 2) fill the constant bank (real device addresses for both symbols)
    void* cwt_dev = nullptr;
    void* stage_dev = nullptr;
    cudaGetSymbolAddress(&cwt_dev, cwt);
    cudaGetSymbolAddress(&stage_dev, g_stage);
    cudaMemcpyAsync(cwt_dev, stage_dev, NCONST * sizeof(u64),
                    cudaMemcpyDeviceToDevice);

    // 3) main kernel
    cudaFuncSetAttribute(osero_kernel,
                         cudaFuncAttributeMaxDynamicSharedMemorySize, SMEM_BYTES);
    osero_kernel<<<blocks, TPB, SMEM_BYTES>>>(edge, cross, corner, cn,
                                              eW1, eb1, xW1, xb1, cW1, cb1,
                                              (float*)d_out);
}